// round 1
// baseline (speedup 1.0000x reference)
#include <cuda_runtime.h>
#include <cuda_fp16.h>
#include <cstdint>

// Problem constants
#define TOKENS   64
#define NFEAT    8192
#define KFEAT    8192

// GEMM tiling
#define KSPLIT    4
#define K_PER_CTA (KFEAT / KSPLIT)      // 2048
#define CTA_N     128                   // 8 warps x 16 cols
#define KC        32                    // K chunk per iteration
#define NCHUNK    (K_PER_CTA / KC)      // 64
#define PITCH     40                    // halves per smem A row (80B, conflict-free ldmatrix)

// Scratch (static device allocations are allowed)
__device__ __align__(16) __half g_x16[TOKENS * KFEAT];               // 1 MB
__device__ __align__(16) float  g_part[KSPLIT][TOKENS * NFEAT];      // 8 MB

// ---------------------------------------------------------------------------
// Kernel 1: convert x (fp32) -> fp16 scratch
// ---------------------------------------------------------------------------
__global__ void cvt_x_kernel(const float* __restrict__ x) {
    int i = blockIdx.x * blockDim.x + threadIdx.x;     // float4 units, 131072 total
    float4 v = reinterpret_cast<const float4*>(x)[i];
    __half2 h0 = __floats2half2_rn(v.x, v.y);
    __half2 h1 = __floats2half2_rn(v.z, v.w);
    reinterpret_cast<__half2*>(g_x16)[i * 2 + 0] = h0;
    reinterpret_cast<__half2*>(g_x16)[i * 2 + 1] = h1;
}

// ---------------------------------------------------------------------------
// Helpers
// ---------------------------------------------------------------------------
__device__ __forceinline__ void cpa16(uint32_t dst, const void* src) {
    asm volatile("cp.async.ca.shared.global [%0], [%1], 16;\n" :: "r"(dst), "l"(src));
}

// Two int32 codes (byte0 valid, rest zero) -> half2 {q0-zp, q1-zp} exactly.
// 0x6400|b as fp16 bits = 1024+b; subtract (1024+zp) -> q-zp (exact, |.|<=155).
__device__ __forceinline__ uint32_t cvt_pair(uint32_t qa, uint32_t qb, uint32_t zpk) {
    uint32_t pk;
    asm("prmt.b32 %0, %1, %2, 0x1410;" : "=r"(pk) : "r"(qa), "r"(qb)); // [qa.b0, 0, qb.b0, 0]
    pk |= 0x64006400u;
    __half2 h = __hsub2(*reinterpret_cast<__half2*>(&pk),
                        *reinterpret_cast<const __half2*>(&zpk));
    return *reinterpret_cast<uint32_t*>(&h);
}

__device__ __forceinline__ void mma16816(float* d, const uint32_t* a, uint32_t b0, uint32_t b1) {
    asm volatile(
        "mma.sync.aligned.m16n8k16.row.col.f32.f16.f16.f32 "
        "{%0,%1,%2,%3},{%4,%5,%6,%7},{%8,%9},{%0,%1,%2,%3};"
        : "+f"(d[0]), "+f"(d[1]), "+f"(d[2]), "+f"(d[3])
        : "r"(a[0]), "r"(a[1]), "r"(a[2]), "r"(a[3]), "r"(b0), "r"(b1));
}

// ---------------------------------------------------------------------------
// Kernel 2: dequant GEMM. Each CTA: 128 output channels x 64 tokens x 2048 K.
// Writes raw dot products sum_k (q-zp)*x16 to g_part[ksplit].
// ---------------------------------------------------------------------------
__global__ __launch_bounds__(256, 2) void gemm_kernel(const int* __restrict__ q,
                                                      const int* __restrict__ zp) {
    __shared__ __align__(16) __half sA[2][TOKENS * PITCH];   // 2 x 5120 B

    const int tid  = threadIdx.x;
    const int warp = tid >> 5;
    const int lane = tid & 31;

    const int n0 = blockIdx.x * CTA_N + warp * 16;   // warp's first output channel
    const int kb = blockIdx.y * K_PER_CTA;           // K-split base

    // B fragment rows (n = lane/4 within each 8-wide frag)
    const int r0  = n0 + (lane >> 2);                // nf = 0
    const int r1  = r0 + 8;                          // nf = 1
    const int kc2 = (lane & 3) * 2;                  // k pair offset within k16

    const int* pB0 = q + (long)r0 * KFEAT + kb + kc2;
    const int* pB1 = q + (long)r1 * KFEAT + kb + kc2;

    // per-row packed (1024+zp) fp16x2
    uint32_t hz[2];
    hz[0] = (0x6400u | (uint32_t)zp[r0]) * 0x10001u;
    hz[1] = (0x6400u | (uint32_t)zp[r1]) * 0x10001u;

    // A staging (cp.async): 256 threads cover 64 rows x 4 segs of 16B (KC=32 halves)
    const int arow = tid >> 2;
    const int aseg = tid & 3;
    const __half* asrc = g_x16 + (long)arow * KFEAT + kb + aseg * 8;
    const uint32_t sbase = (uint32_t)__cvta_generic_to_shared(&sA[0][0]);
    const uint32_t BUFB  = TOKENS * PITCH * 2;                   // bytes per buffer
    const uint32_t adst  = (uint32_t)(arow * PITCH + aseg * 8) * 2;

    // ---- prologue: chunk 0 in flight ----
    cpa16(sbase + adst, asrc);
    asm volatile("cp.async.commit_group;\n");

    int2 raw[2][2][2];   // [nf][s][pair] : raw int32 codes for one chunk
#pragma unroll
    for (int s = 0; s < 2; s++)
#pragma unroll
        for (int p = 0; p < 2; p++) {
            raw[0][s][p] = __ldcs((const int2*)(pB0 + s * 16 + p * 8));
            raw[1][s][p] = __ldcs((const int2*)(pB1 + s * 16 + p * 8));
        }

    float acc[4][2][4];
#pragma unroll
    for (int mi = 0; mi < 4; mi++)
#pragma unroll
        for (int nf = 0; nf < 2; nf++)
#pragma unroll
            for (int j = 0; j < 4; j++) acc[mi][nf][j] = 0.f;

    int buf = 0;
    for (int c = 0; c < NCHUNK; ++c) {
        asm volatile("cp.async.wait_group 0;\n" ::: "memory");
        __syncthreads();

        // prefetch next A chunk into the other buffer
        if (c + 1 < NCHUNK) {
            cpa16(sbase + (buf ^ 1) * BUFB + adst, asrc + (c + 1) * KC);
            asm volatile("cp.async.commit_group;\n");
        }

        // convert this chunk's raw B codes to fp16 fragments
        uint32_t bf[2][2][2];
#pragma unroll
        for (int nf = 0; nf < 2; nf++)
#pragma unroll
            for (int s = 0; s < 2; s++)
#pragma unroll
                for (int p = 0; p < 2; p++)
                    bf[nf][s][p] = cvt_pair((uint32_t)raw[nf][s][p].x,
                                            (uint32_t)raw[nf][s][p].y, hz[nf]);

        // prefetch next chunk's raw B codes
        if (c + 1 < NCHUNK) {
            const int off = (c + 1) * KC;
#pragma unroll
            for (int s = 0; s < 2; s++)
#pragma unroll
                for (int p = 0; p < 2; p++) {
                    raw[0][s][p] = __ldcs((const int2*)(pB0 + off + s * 16 + p * 8));
                    raw[1][s][p] = __ldcs((const int2*)(pB1 + off + s * 16 + p * 8));
                }
        }

        // compute: 2 k16 steps x 4 m-tiles x 2 n-frags
        const uint32_t abase = sbase + buf * BUFB;
        const int rl = lane & 15;
        const int kh = (lane >> 4) * 8;
#pragma unroll
        for (int s = 0; s < 2; s++) {
            uint32_t a[4][4];
#pragma unroll
            for (int mi = 0; mi < 4; mi++) {
                uint32_t addr = abase + (uint32_t)(((mi * 16 + rl) * PITCH) + s * 16 + kh) * 2;
                asm volatile(
                    "ldmatrix.sync.aligned.m8n8.x4.shared.b16 {%0,%1,%2,%3}, [%4];"
                    : "=r"(a[mi][0]), "=r"(a[mi][1]), "=r"(a[mi][2]), "=r"(a[mi][3])
                    : "r"(addr));
            }
#pragma unroll
            for (int mi = 0; mi < 4; mi++)
#pragma unroll
                for (int nf = 0; nf < 2; nf++)
                    mma16816(acc[mi][nf], a[mi], bf[nf][s][0], bf[nf][s][1]);
        }
        buf ^= 1;
    }

    // epilogue: store raw partial dots (deterministic, no atomics)
    float* pp = &g_part[blockIdx.y][0];
#pragma unroll
    for (int mi = 0; mi < 4; mi++)
#pragma unroll
        for (int nf = 0; nf < 2; nf++) {
            int col = n0 + nf * 8 + kc2;
            int t0  = mi * 16 + (lane >> 2);
            float2 v0 = make_float2(acc[mi][nf][0], acc[mi][nf][1]);
            float2 v1 = make_float2(acc[mi][nf][2], acc[mi][nf][3]);
            *reinterpret_cast<float2*>(&pp[(long)t0 * NFEAT + col])       = v0;
            *reinterpret_cast<float2*>(&pp[(long)(t0 + 8) * NFEAT + col]) = v1;
        }
}

// ---------------------------------------------------------------------------
// Kernel 3: reduce K-splits, apply scale + bias
// ---------------------------------------------------------------------------
__global__ void reduce_kernel(const float* __restrict__ scales,
                              const float* __restrict__ bias,
                              float* __restrict__ out) {
    int i = blockIdx.x * blockDim.x + threadIdx.x;     // float4 units, 131072 total
    float4 a = reinterpret_cast<const float4*>(g_part[0])[i];
    float4 b = reinterpret_cast<const float4*>(g_part[1])[i];
    float4 c = reinterpret_cast<const float4*>(g_part[2])[i];
    float4 d = reinterpret_cast<const float4*>(g_part[3])[i];
    int col4 = i & (NFEAT / 4 - 1);
    float4 sc = reinterpret_cast<const float4*>(scales)[col4];
    float4 bi = reinterpret_cast<const float4*>(bias)[col4];
    float4 r;
    r.x = bi.x + sc.x * (a.x + b.x + c.x + d.x);
    r.y = bi.y + sc.y * (a.y + b.y + c.y + d.y);
    r.z = bi.z + sc.z * (a.z + b.z + c.z + d.z);
    r.w = bi.w + sc.w * (a.w + b.w + c.w + d.w);
    reinterpret_cast<float4*>(out)[i] = r;
}

// ---------------------------------------------------------------------------
extern "C" void kernel_launch(void* const* d_in, const int* in_sizes, int n_in,
                              void* d_out, int out_size) {
    const float* x     = (const float*)d_in[0];
    const int*   qw    = (const int*)d_in[1];
    const float* sc    = (const float*)d_in[2];
    const int*   zp    = (const int*)d_in[3];
    const float* bias  = (const float*)d_in[4];
    float*       out   = (float*)d_out;

    (void)in_sizes; (void)n_in; (void)out_size;

    cvt_x_kernel<<<(TOKENS * KFEAT / 4) / 256, 256>>>(x);
    gemm_kernel<<<dim3(NFEAT / CTA_N, KSPLIT), 256>>>(qw, zp);
    reduce_kernel<<<(TOKENS * NFEAT / 4) / 256, 256>>>(sc, bias, out);
}